// round 10
// baseline (speedup 1.0000x reference)
#include <cuda_runtime.h>
#include <cuda_bf16.h>

#define N_NODES 16384
#define N_EDGES 524288
#define HID 256
#define HHALF 128
#define R2 2500.0f
#define EPSV 1e-8f
#define NPB 32
#define GRIDC 20
#define NCELLS (GRIDC * GRIDC)

#define NBLK 296                 // 2 per SM on 148 SMs — co-resident guaranteed
#define NTHR 256
#define GTOT (NBLK * NTHR)       // 75776 threads
#define NWARP (GTOT / 32)        // 2368 warps

// ---------------- scratch ---------------------------------------------------
__device__ int    g_deg[N_NODES];
__device__ int    g_slot[N_EDGES];
__device__ int    g_csr_ptr[N_NODES + 1];
__device__ int    g_csr_col[N_EDGES];
__device__ float  g_density[N_NODES];
__device__ float  g_fvar[N_NODES];
__device__ float  g_max[4];
__device__ unsigned int g_xh[N_NODES * HHALF];
__device__ int    g_cell_cnt[NCELLS];
__device__ int    g_cell_fill[NCELLS];
__device__ int    g_cell_ptr[NCELLS + 1];
__device__ int    g_node_cell[N_NODES];
__device__ float2 g_sorted_xy[N_NODES];
__device__ int    g_sorted_id[N_NODES];
// grid barrier state
__device__ int            g_bar_count = 0;
__device__ volatile int   g_bar_gen   = 0;

__device__ __forceinline__ int cell_of(float v) {
    int c = (int)(v * 0.02f);
    return min(max(c, 0), GRIDC - 1);
}
__device__ __forceinline__ unsigned int pack_bf(float lo, float hi) {
    unsigned int l = (unsigned int)__bfloat16_as_ushort(__float2bfloat16(lo));
    unsigned int h = (unsigned int)__bfloat16_as_ushort(__float2bfloat16(hi));
    return l | (h << 16);
}
__device__ __forceinline__ void bfacc(unsigned int u, float& a, float& b) {
    a += __uint_as_float(u << 16);
    b += __uint_as_float(u & 0xFFFF0000u);
}
__device__ __forceinline__ unsigned long long pk2(float a, float b) {
    unsigned long long r;
    asm("mov.b64 %0, {%1, %2};" : "=l"(r) : "f"(a), "f"(b));
    return r;
}
__device__ __forceinline__ void fma2(unsigned long long& d,
                                     unsigned long long a, unsigned long long b) {
    asm("fma.rn.f32x2 %0, %1, %2, %0;" : "+l"(d) : "l"(a), "l"(b));
}
__device__ __forceinline__ float2 upk(unsigned long long v) {
    float2 f;
    asm("mov.b64 {%0, %1}, %2;" : "=f"(f.x), "=f"(f.y) : "l"(v));
    return f;
}

// grid-wide barrier: all threads fence, block arrives once, spin on generation
__device__ __forceinline__ void grid_sync() {
    __threadfence();                    // release: every thread's writes
    __syncthreads();
    if (threadIdx.x == 0) {
        int gen = g_bar_gen;
        if (atomicAdd(&g_bar_count, 1) == NBLK - 1) {
            g_bar_count = 0;
            __threadfence();
            g_bar_gen = gen + 1;
        } else {
            while (g_bar_gen == gen) __nanosleep(64);
        }
    }
    __syncthreads();
}

__shared__ __align__(16) float s_hid[HHALF][NPB];
__shared__ float s_feats[NPB][3];
__shared__ int   s_wt[32];
__shared__ int   s_wm[32];

__global__ void __launch_bounds__(NTHR, 2) k_all(
    const float4* __restrict__ x4, const int* __restrict__ row,
    const int* __restrict__ col, const float2* __restrict__ coords,
    const float* __restrict__ w1, const float* __restrict__ b1,
    const float* __restrict__ w2, const float* __restrict__ b2,
    float* __restrict__ out)
{
    const int t = threadIdx.x, b = blockIdx.x;
    const int gtid = b * NTHR + t;
    const int lane = t & 31;
    const int warp = t >> 5;

    // ---------------- P0: zero ----------------
    for (int i = gtid; i < N_NODES; i += GTOT) g_deg[i] = 0;
    if (gtid < NCELLS) { g_cell_cnt[gtid] = 0; g_cell_fill[gtid] = 0; }
    if (gtid < 4) g_max[gtid] = 0.0f;
    grid_sync();

    // ---------------- P1: bin hist || degree+slot || bf16 convert ----------
    for (int i = gtid; i < N_NODES; i += GTOT) {
        float2 p = coords[i];
        int c = cell_of(p.y) * GRIDC + cell_of(p.x);
        g_node_cell[i] = c;
        atomicAdd(&g_cell_cnt[c], 1);
    }
    for (int i = gtid; i < N_EDGES / 2; i += GTOT) {
        int2 r2 = ((const int2*)row)[i];
        int s0 = atomicAdd(&g_deg[r2.x], 1);
        int s1 = atomicAdd(&g_deg[r2.y], 1);
        ((int2*)g_slot)[i] = make_int2(s0, s1);
    }
    for (int i = gtid; i < (N_NODES * HHALF) / 4; i += GTOT) {
        float4 a = x4[2 * i];
        float4 c = x4[2 * i + 1];
        uint4 o;
        o.x = pack_bf(a.x, a.y);
        o.y = pack_bf(a.z, a.w);
        o.z = pack_bf(c.x, c.y);
        o.w = pack_bf(c.z, c.w);
        ((uint4*)g_xh)[i] = o;
    }
    grid_sync();

    // ---------------- P2: scans (block 0: cells, block 1: degrees) ---------
    if (b == 0) {
        if (t < 32) {                      // single warp, 13 cells per lane
            int base = t * 13;
            int loc[13];
            int sum = 0;
#pragma unroll
            for (int k = 0; k < 13; k++) {
                int c = base + k;
                int v = (c < NCELLS) ? g_cell_cnt[c] : 0;
                loc[k] = sum; sum += v;
            }
            int s = sum;
#pragma unroll
            for (int o = 1; o < 32; o <<= 1) {
                int u = __shfl_up_sync(0xFFFFFFFFu, s, o);
                if (t >= o) s += u;
            }
            int excl = s - sum;
#pragma unroll
            for (int k = 0; k < 13; k++) {
                int c = base + k;
                if (c < NCELLS) g_cell_ptr[c] = excl + loc[k];
            }
            if (t == 31) g_cell_ptr[NCELLS] = s;
        }
    } else if (b == 1) {
        // 256 threads x 64 degrees, two passes (sum+max, then prefix write)
        int base = t * 64;
        int sum = 0, m = 0;
        for (int k = 0; k < 64; k++) {
            int d = g_deg[base + k];
            sum += d; m = max(m, d);
        }
        int s = sum;
#pragma unroll
        for (int o = 1; o < 32; o <<= 1) {
            int u = __shfl_up_sync(0xFFFFFFFFu, s, o);
            if (lane >= o) s += u;
        }
#pragma unroll
        for (int o = 16; o > 0; o >>= 1)
            m = max(m, __shfl_down_sync(0xFFFFFFFFu, m, o));
        if (lane == 31) s_wt[warp] = s;
        if (lane == 0)  s_wm[warp] = m;
        __syncthreads();
        if (warp == 0 && lane < 8) {
            int w = s_wt[lane];
#pragma unroll
            for (int o = 1; o < 8; o <<= 1) {
                int u = __shfl_up_sync(0xFFu, w, o);
                if (lane >= o) w += u;
            }
            s_wt[lane] = w;
            int mm = s_wm[lane];
#pragma unroll
            for (int o = 4; o > 0; o >>= 1)
                mm = max(mm, __shfl_down_sync(0xFFu, mm, o));
            if (lane == 0) g_max[0] = (float)mm;
        }
        __syncthreads();
        int excl = s - sum + (warp > 0 ? s_wt[warp - 1] : 0);
        int run = excl;
        for (int k = 0; k < 64; k++) {
            int d = g_deg[base + k];
            g_csr_ptr[base + k] = run;
            run += d;
        }
        if (t == 255) g_csr_ptr[N_NODES] = run;
    }
    grid_sync();

    // ---------------- P3: bin fill || CSR fill ------------------------------
    for (int i = gtid; i < N_NODES; i += GTOT) {
        int c = g_node_cell[i];
        int pos = g_cell_ptr[c] + atomicAdd(&g_cell_fill[c], 1);
        g_sorted_xy[pos] = coords[i];
        g_sorted_id[pos] = i;
    }
    for (int i = gtid; i < N_EDGES / 2; i += GTOT) {
        int2 r2 = ((const int2*)row)[i];
        int2 c2 = ((const int2*)col)[i];
        int2 s2 = ((const int2*)g_slot)[i];
        g_csr_col[g_csr_ptr[r2.x] + s2.x] = c2.x;
        g_csr_col[g_csr_ptr[r2.y] + s2.y] = c2.y;
    }
    grid_sync();

    // ---------------- P4: density (thread-strided) + fvar (warp-strided) ---
    {
        float dmax = 0.0f;
        for (int i = gtid; i < N_NODES; i += GTOT) {
            float2 p = g_sorted_xy[i];
            int cx = cell_of(p.x), cy = cell_of(p.y);
            int y0 = max(cy - 1, 0), y1 = min(cy + 1, GRIDC - 1);
            int x0 = max(cx - 1, 0), x1 = min(cx + 1, GRIDC - 1);
            int cnt = 0;
            for (int yy = y0; yy <= y1; yy++) {
                int bb = g_cell_ptr[yy * GRIDC + x0];
                int ee = g_cell_ptr[yy * GRIDC + x1 + 1];
                for (int k = bb; k < ee; k++) {
                    float2 q = g_sorted_xy[k];
                    float dx = p.x - q.x;
                    float dy = p.y - q.y;
                    cnt += (fmaf(dx, dx, dy * dy) <= R2) ? 1 : 0;
                }
            }
            g_density[g_sorted_id[i]] = (float)cnt;
            dmax = fmaxf(dmax, (float)(cnt - 1));
        }
#pragma unroll
        for (int off = 16; off > 0; off >>= 1)
            dmax = fmaxf(dmax, __shfl_down_sync(0xFFFFFFFFu, dmax, off));
        if (lane == 0) atomicMax((int*)&g_max[1], __float_as_int(dmax));
    }
    {
        const uint4* xh = (const uint4*)g_xh;
        int wg = gtid >> 5;
        float fmax_loc = 0.0f;
        for (int n = wg; n < N_NODES; n += NWARP) {
            int beg = g_csr_ptr[n], end = g_csr_ptr[n + 1];
            float s0 = 0, s1 = 0, s2 = 0, s3 = 0, s4 = 0, s5 = 0, s6 = 0, s7 = 0;
            int e = beg;
            for (; e + 8 <= end; e += 8) {
                int cc[8];
#pragma unroll
                for (int k = 0; k < 8; k++) cc[k] = g_csr_col[e + k];
                uint4 vv[8];
#pragma unroll
                for (int k = 0; k < 8; k++) vv[k] = xh[cc[k] * 32 + lane];
#pragma unroll
                for (int k = 0; k < 8; k++) {
                    bfacc(vv[k].x, s0, s1); bfacc(vv[k].y, s2, s3);
                    bfacc(vv[k].z, s4, s5); bfacc(vv[k].w, s6, s7);
                }
            }
            for (; e < end; e++) {
                uint4 v = xh[g_csr_col[e] * 32 + lane];
                bfacc(v.x, s0, s1); bfacc(v.y, s2, s3);
                bfacc(v.z, s4, s5); bfacc(v.w, s6, s7);
            }
            float inv = 1.0f / (float)((end - beg) > 1 ? (end - beg) : 1);
            float4 xa = x4[n * 64 + lane * 2];
            float4 xb = x4[n * 64 + lane * 2 + 1];
            float d0 = xa.x - s0 * inv, d1 = xa.y - s1 * inv;
            float d2 = xa.z - s2 * inv, d3 = xa.w - s3 * inv;
            float d4 = xb.x - s4 * inv, d5 = xb.y - s5 * inv;
            float d6 = xb.z - s6 * inv, d7 = xb.w - s7 * inv;
            float local = fmaf(d0, d0, fmaf(d1, d1, fmaf(d2, d2, d3 * d3)))
                        + fmaf(d4, d4, fmaf(d5, d5, fmaf(d6, d6, d7 * d7)));
#pragma unroll
            for (int off = 16; off > 0; off >>= 1)
                local += __shfl_down_sync(0xFFFFFFFFu, local, off);
            if (lane == 0) {
                float fv = sqrtf(local);
                g_fvar[n] = fv;
                fmax_loc = fmaxf(fmax_loc, fv);
            }
        }
        if (lane == 0) atomicMax((int*)&g_max[2], __float_as_int(fmax_loc));
    }
    grid_sync();

    // ---------------- P5: MLP, block-strided over 32-node tiles -------------
    for (int tile = b; tile < N_NODES / NPB; tile += NBLK) {
        int n0 = tile * NPB;
        if (t < NPB) {
            int n = n0 + t;
            float invd   = 1.0f / (g_max[0] + EPSV);
            float invden = 1.0f / (g_max[1] + EPSV);
            float invf   = 1.0f / (g_max[2] + EPSV);
            s_feats[t][0] = (float)g_deg[n] * invd;
            s_feats[t][1] = (g_density[n] - 1.0f) * invden;
            s_feats[t][2] = g_fvar[n] * invf;
        }
        __syncthreads();

        for (int idx = t; idx < NPB * HHALF; idx += NTHR) {
            int j = idx & (HHALF - 1);
            int node = idx >> 7;
            float v = b1[j]
                    + s_feats[node][0] * w1[j]
                    + s_feats[node][1] * w1[HHALF + j]
                    + s_feats[node][2] * w1[2 * HHALF + j];
            s_hid[j][node] = fmaxf(v, 0.0f);
        }
        __syncthreads();

        int c = t;
        unsigned long long acc[NPB / 2];
        float bc = b2[c];
        unsigned long long bcc = pk2(bc, bc);
#pragma unroll
        for (int p = 0; p < NPB / 2; p++) acc[p] = bcc;

        for (int j = 0; j < HHALF; j++) {
            float wj = w2[j * HID + c];
            unsigned long long wjj = pk2(wj, wj);
            const ulonglong2* hv = (const ulonglong2*)&s_hid[j][0];
#pragma unroll
            for (int q = 0; q < NPB / 4; q++) {
                ulonglong2 h2 = hv[q];
                fma2(acc[2 * q + 0], h2.x, wjj);
                fma2(acc[2 * q + 1], h2.y, wjj);
            }
        }
#pragma unroll
        for (int p = 0; p < NPB / 2; p++) {
            float2 v = upk(acc[p]);
            out[(n0 + 2 * p) * HID + c]     = v.x;
            out[(n0 + 2 * p + 1) * HID + c] = v.y;
        }
        __syncthreads();   // protect s_hid before next tile
    }
}

// ---------------- launch ----------------------------------------------------
extern "C" void kernel_launch(void* const* d_in, const int* in_sizes, int n_in,
                              void* d_out, int out_size) {
    const float*  x      = (const float*)d_in[0];
    const int*    ei     = (const int*)d_in[1];
    const float2* coords = (const float2*)d_in[2];
    const float*  w1     = (const float*)d_in[3];
    const float*  b1     = (const float*)d_in[4];
    const float*  w2     = (const float*)d_in[5];
    const float*  b2     = (const float*)d_in[6];
    float*        out    = (float*)d_out;

    const int* row = ei;
    const int* col = ei + N_EDGES;

    k_all<<<NBLK, NTHR>>>((const float4*)x, row, col, coords, w1, b1, w2, b2, out);
}

// round 11
// speedup vs baseline: 1.6145x; 1.6145x over previous
#include <cuda_runtime.h>
#include <cuda_bf16.h>
#include <mma.h>

using namespace nvcuda;

#define N_NODES 16384
#define N_EDGES 524288
#define HID 256
#define HHALF 128
#define R2 2500.0f
#define EPSV 1e-8f
#define NPB 64      // nodes per block in MLP kernel
#define GRIDC 20
#define NCELLS (GRIDC * GRIDC)

// ---------------- scratch (device globals, zero-initialized at load) -------
__device__ int    g_deg[N_NODES];          // re-zeroed by k_mlp each call
__device__ int    g_slot[N_EDGES];
__device__ int    g_csr_ptr[N_NODES + 1];
__device__ int    g_csr_col[N_EDGES];
__device__ float  g_density[N_NODES];
__device__ float  g_fvar[N_NODES];
__device__ float  g_max[4];                // [1],[2] re-zeroed by k_scans
__device__ unsigned int g_xh[N_NODES * HHALF];
__device__ float  g_b2rep[16 * HID];       // b2 replicated over 16 rows (C-frag init)
__device__ int    g_cell_cnt[NCELLS];      // re-zeroed by k_mlp block 0
__device__ int    g_cell_fill[NCELLS];     // re-zeroed by k_mlp block 0
__device__ int    g_cell_ptr[NCELLS + 1];
__device__ int    g_node_cell[N_NODES];
__device__ float2 g_sorted_xy[N_NODES];
__device__ int    g_sorted_id[N_NODES];

__device__ __forceinline__ int cell_of(float v) {
    int c = (int)(v * 0.02f);
    return min(max(c, 0), GRIDC - 1);
}
__device__ __forceinline__ unsigned int pack_bf(float lo, float hi) {
    unsigned int l = (unsigned int)__bfloat16_as_ushort(__float2bfloat16(lo));
    unsigned int h = (unsigned int)__bfloat16_as_ushort(__float2bfloat16(hi));
    return l | (h << 16);
}
__device__ __forceinline__ void bfacc(unsigned int u, float& a, float& b) {
    a += __uint_as_float(u << 16);
    b += __uint_as_float(u & 0xFFFF0000u);
}

// ---------------- K1: fused counts (bins || degree+slot || convert || b2rep)
// blocks [0,64): bins; [64,1088): degree 2e/thr; [1088,3136): convert; 3136: b2rep
__global__ void k_count(const float2* __restrict__ coords, const int* __restrict__ row,
                        const float4* __restrict__ x4, const float* __restrict__ b2) {
    int b = blockIdx.x, t = threadIdx.x;
    if (b < 64) {
        int i = b * 256 + t;
        float2 p = coords[i];
        int c = cell_of(p.y) * GRIDC + cell_of(p.x);
        g_node_cell[i] = c;
        atomicAdd(&g_cell_cnt[c], 1);
    } else if (b < 64 + 1024) {
        int idx = (b - 64) * 256 + t;
        int2 r2 = ((const int2*)row)[idx];
        int s0 = atomicAdd(&g_deg[r2.x], 1);
        int s1 = atomicAdd(&g_deg[r2.y], 1);
        ((int2*)g_slot)[idx] = make_int2(s0, s1);
    } else if (b < 3136) {
        int idx = (b - 1088) * 256 + t;
        float4 a = x4[2 * idx];
        float4 c = x4[2 * idx + 1];
        uint4 o;
        o.x = pack_bf(a.x, a.y);
        o.y = pack_bf(a.z, a.w);
        o.z = pack_bf(c.x, c.y);
        o.w = pack_bf(c.z, c.w);
        ((uint4*)g_xh)[idx] = o;
    } else {
        float v = b2[t];
#pragma unroll
        for (int r = 0; r < 16; r++) g_b2rep[r * HID + t] = v;
    }
}

// ---------------- K2: fused scans + g_max[1..2] reset ------------------------
__global__ void k_scans() {
    int t = threadIdx.x;
    int lane = t & 31, warp = t >> 5;
    if (blockIdx.x == 0) {
        if (t < 2) g_max[1 + t] = 0.0f;          // reset for atomicMax
        int v = (t < NCELLS) ? g_cell_cnt[t] : 0;
        int s = v;
#pragma unroll
        for (int o = 1; o < 32; o <<= 1) {
            int u = __shfl_up_sync(0xFFFFFFFFu, s, o);
            if (lane >= o) s += u;
        }
        __shared__ int wt[32];
        if (lane == 31) wt[warp] = s;
        __syncthreads();
        if (warp == 0) {
            int w = wt[lane];
#pragma unroll
            for (int o = 1; o < 32; o <<= 1) {
                int u = __shfl_up_sync(0xFFFFFFFFu, w, o);
                if (lane >= o) w += u;
            }
            wt[lane] = w;
        }
        __syncthreads();
        int incl = s + (warp > 0 ? wt[warp - 1] : 0);
        if (t < NCELLS) g_cell_ptr[t] = incl - v;
        if (t == NCELLS - 1) g_cell_ptr[NCELLS] = incl;
    } else {
        int base = t * 16;
        int loc[16];
        int sum = 0, m = 0;
#pragma unroll
        for (int k = 0; k < 16; k++) {
            int d = g_deg[base + k];
            loc[k] = sum; sum += d; m = max(m, d);
        }
        int s = sum;
#pragma unroll
        for (int o = 1; o < 32; o <<= 1) {
            int u = __shfl_up_sync(0xFFFFFFFFu, s, o);
            if (lane >= o) s += u;
        }
#pragma unroll
        for (int o = 16; o > 0; o >>= 1)
            m = max(m, __shfl_down_sync(0xFFFFFFFFu, m, o));
        __shared__ int wt[32];
        __shared__ int wm[32];
        if (lane == 31) wt[warp] = s;
        if (lane == 0) wm[warp] = m;
        __syncthreads();
        if (warp == 0) {
            int w = wt[lane];
#pragma unroll
            for (int o = 1; o < 32; o <<= 1) {
                int u = __shfl_up_sync(0xFFFFFFFFu, w, o);
                if (lane >= o) w += u;
            }
            wt[lane] = w;
            int mm = wm[lane];
#pragma unroll
            for (int o = 16; o > 0; o >>= 1)
                mm = max(mm, __shfl_down_sync(0xFFFFFFFFu, mm, o));
            if (lane == 0) g_max[0] = (float)mm;
        }
        __syncthreads();
        int excl = s - sum + (warp > 0 ? wt[warp - 1] : 0);
#pragma unroll
        for (int k = 0; k < 16; k++) g_csr_ptr[base + k] = excl + loc[k];
        if (t == 1023) g_csr_ptr[N_NODES] = excl + sum;
    }
}

// ---------------- K3: fused fills (bin fill || CSR fill) --------------------
__global__ void k_fills(const float2* __restrict__ coords,
                        const int* __restrict__ row, const int* __restrict__ col) {
    int b = blockIdx.x, t = threadIdx.x;
    if (b < 64) {
        int i = b * 256 + t;
        int c = g_node_cell[i];
        int pos = g_cell_ptr[c] + atomicAdd(&g_cell_fill[c], 1);
        g_sorted_xy[pos] = coords[i];
        g_sorted_id[pos] = i;
    } else {
        int idx = (b - 64) * 256 + t;
        int2 r2 = ((const int2*)row)[idx];
        int2 c2 = ((const int2*)col)[idx];
        int2 s2 = ((const int2*)g_slot)[idx];
        g_csr_col[g_csr_ptr[r2.x] + s2.x] = c2.x;
        g_csr_col[g_csr_ptr[r2.y] + s2.y] = c2.y;
    }
}

// ---------------- K4: fused density || fvar ---------------------------------
__global__ void k_den_fvar(const float4* __restrict__ x4) {
    int b = blockIdx.x, t = threadIdx.x;
    if (b < 64) {
        int i = b * 256 + t;
        float2 p = g_sorted_xy[i];
        int cx = cell_of(p.x), cy = cell_of(p.y);
        int y0 = max(cy - 1, 0), y1 = min(cy + 1, GRIDC - 1);
        int x0 = max(cx - 1, 0), x1 = min(cx + 1, GRIDC - 1);
        int cnt = 0;
        for (int yy = y0; yy <= y1; yy++) {
            int bb = g_cell_ptr[yy * GRIDC + x0];
            int ee = g_cell_ptr[yy * GRIDC + x1 + 1];
            for (int k = bb; k < ee; k++) {
                float2 q = g_sorted_xy[k];
                float dx = p.x - q.x;
                float dy = p.y - q.y;
                cnt += (fmaf(dx, dx, dy * dy) <= R2) ? 1 : 0;
            }
        }
        g_density[g_sorted_id[i]] = (float)cnt;
        float v = (float)(cnt - 1);
#pragma unroll
        for (int off = 16; off > 0; off >>= 1)
            v = fmaxf(v, __shfl_down_sync(0xFFFFFFFFu, v, off));
        __shared__ float wm[8];
        if ((t & 31) == 0) wm[t >> 5] = v;
        __syncthreads();
        if (t == 0) {
            float m = wm[0];
#pragma unroll
            for (int w = 1; w < 8; w++) m = fmaxf(m, wm[w]);
            atomicMax((int*)&g_max[1], __float_as_int(m));
        }
    } else {
        int warp = t >> 5, lane = t & 31;
        int n = (b - 64) * 8 + warp;
        int beg = g_csr_ptr[n], end = g_csr_ptr[n + 1];
        const uint4* xh = (const uint4*)g_xh;

        float s0 = 0, s1 = 0, s2 = 0, s3 = 0, s4 = 0, s5 = 0, s6 = 0, s7 = 0;
        int e = beg;
        for (; e + 8 <= end; e += 8) {
            int cc[8];
#pragma unroll
            for (int k = 0; k < 8; k++) cc[k] = g_csr_col[e + k];
            uint4 vv[8];
#pragma unroll
            for (int k = 0; k < 8; k++) vv[k] = xh[cc[k] * 32 + lane];
#pragma unroll
            for (int k = 0; k < 8; k++) {
                bfacc(vv[k].x, s0, s1); bfacc(vv[k].y, s2, s3);
                bfacc(vv[k].z, s4, s5); bfacc(vv[k].w, s6, s7);
            }
        }
        for (; e < end; e++) {
            uint4 v = xh[g_csr_col[e] * 32 + lane];
            bfacc(v.x, s0, s1); bfacc(v.y, s2, s3); bfacc(v.z, s4, s5); bfacc(v.w, s6, s7);
        }

        float inv = 1.0f / (float)((end - beg) > 1 ? (end - beg) : 1);
        float4 xa = x4[n * 64 + lane * 2];
        float4 xb = x4[n * 64 + lane * 2 + 1];
        float d0 = xa.x - s0 * inv, d1 = xa.y - s1 * inv;
        float d2 = xa.z - s2 * inv, d3 = xa.w - s3 * inv;
        float d4 = xb.x - s4 * inv, d5 = xb.y - s5 * inv;
        float d6 = xb.z - s6 * inv, d7 = xb.w - s7 * inv;
        float local = fmaf(d0, d0, fmaf(d1, d1, fmaf(d2, d2, d3 * d3)))
                    + fmaf(d4, d4, fmaf(d5, d5, fmaf(d6, d6, d7 * d7)));
#pragma unroll
        for (int off = 16; off > 0; off >>= 1)
            local += __shfl_down_sync(0xFFFFFFFFu, local, off);

        __shared__ float fv8[8];
        if (lane == 0) {
            float fv = sqrtf(local);
            g_fvar[n] = fv;
            fv8[warp] = fv;
        }
        __syncthreads();
        if (t == 0) {
            float m = fv8[0];
#pragma unroll
            for (int w = 1; w < 8; w++) m = fmaxf(m, fv8[w]);
            atomicMax((int*)&g_max[2], __float_as_int(m));
        }
    }
}

// ---------------- K5: MLP — hidden in smem fp32, output via tf32 WMMA -------
// 64 nodes/block, 256 threads (8 warps). Also recycles g_deg / cells to zero.
__global__ void k_mlp(const float* __restrict__ w1, const float* __restrict__ b1,
                      const float* __restrict__ w2, float* __restrict__ out) {
    __shared__ float s_feats[NPB][3];
    __shared__ __align__(16) float s_hid[NPB][HHALF];   // row-major [node][j]
    int t = threadIdx.x;
    int n0 = blockIdx.x * NPB;

    if (t < NPB) {
        int n = n0 + t;
        float invd   = 1.0f / (g_max[0] + EPSV);
        float invden = 1.0f / (g_max[1] + EPSV);
        float invf   = 1.0f / (g_max[2] + EPSV);
        s_feats[t][0] = (float)g_deg[n] * invd;
        s_feats[t][1] = (g_density[n] - 1.0f) * invden;
        s_feats[t][2] = g_fvar[n] * invf;
        g_deg[n] = 0;                       // recycle for next call (own node)
    }
    if (blockIdx.x == 0) {                  // recycle cells (mlp never reads them)
        for (int i = t; i < NCELLS; i += 256) { g_cell_cnt[i] = 0; g_cell_fill[i] = 0; }
    }
    __syncthreads();

    // hidden layer: 64 nodes x 128 features, fp32
    for (int idx = t; idx < NPB * HHALF; idx += 256) {
        int j = idx & (HHALF - 1);
        int node = idx >> 7;
        float v = b1[j]
                + s_feats[node][0] * w1[j]
                + s_feats[node][1] * w1[HHALF + j]
                + s_feats[node][2] * w1[2 * HHALF + j];
        s_hid[node][j] = fmaxf(v, 0.0f);
    }
    __syncthreads();

    // output: [64 x 128] @ [128 x 256] + b2, tf32 HMMA
    int warp = t >> 5;
    int msub = warp & 3;                    // 4 M-subtiles of 16 rows
    int nbase = (warp >> 2) * 8;            // 2 N-halves of 8 tiles (16 cols each)

    wmma::fragment<wmma::accumulator, 16, 16, 8, float> cf[8];
#pragma unroll
    for (int i = 0; i < 8; i++)
        wmma::load_matrix_sync(cf[i], g_b2rep + (nbase + i) * 16, HID, wmma::mem_row_major);

    for (int k = 0; k < 16; k++) {
        wmma::fragment<wmma::matrix_a, 16, 16, 8, wmma::precision::tf32, wmma::row_major> af;
        wmma::load_matrix_sync(af, &s_hid[msub * 16][k * 8], HHALF);
#pragma unroll
        for (int e = 0; e < af.num_elements; e++) af.x[e] = wmma::__float_to_tf32(af.x[e]);
#pragma unroll
        for (int i = 0; i < 8; i++) {
            wmma::fragment<wmma::matrix_b, 16, 16, 8, wmma::precision::tf32, wmma::row_major> bf;
            wmma::load_matrix_sync(bf, w2 + (k * 8) * HID + (nbase + i) * 16, HID);
#pragma unroll
            for (int e = 0; e < bf.num_elements; e++) bf.x[e] = wmma::__float_to_tf32(bf.x[e]);
            wmma::mma_sync(cf[i], af, bf, cf[i]);
        }
    }
#pragma unroll
    for (int i = 0; i < 8; i++)
        wmma::store_matrix_sync(out + (n0 + msub * 16) * HID + (nbase + i) * 16,
                                cf[i], HID, wmma::mem_row_major);
}

// ---------------- launch ----------------------------------------------------
extern "C" void kernel_launch(void* const* d_in, const int* in_sizes, int n_in,
                              void* d_out, int out_size) {
    const float*  x      = (const float*)d_in[0];
    const int*    ei     = (const int*)d_in[1];
    const float2* coords = (const float2*)d_in[2];
    const float*  w1     = (const float*)d_in[3];
    const float*  b1     = (const float*)d_in[4];
    const float*  w2     = (const float*)d_in[5];
    const float*  b2     = (const float*)d_in[6];
    float*        out    = (float*)d_out;

    const int* row = ei;
    const int* col = ei + N_EDGES;

    k_count   <<<3137, 256>>>(coords, row, (const float4*)x, b2);
    k_scans   <<<2, 1024>>>();
    k_fills   <<<64 + 1024, 256>>>(coords, row, col);
    k_den_fvar<<<64 + 2048, 256>>>((const float4*)x);
    k_mlp     <<<N_NODES / NPB, 256>>>(w1, b1, w2, out);
}